// round 10
// baseline (speedup 1.0000x reference)
#include <cuda_runtime.h>
#include <math.h>
#include <stdint.h>

#define S_LEN 3744
#define DIM 1536
#define NH 12
#define HD 128
#define HH 26
#define WW 48
#define EPSN 1e-6f

// scratch (allocation-free rule: __device__ globals)
__device__ float g_q[S_LEN * DIM];
__device__ float g_k[S_LEN * DIM];
__device__ float g_v[S_LEN * DIM];
__device__ float g_o[S_LEN * DIM];
__device__ float g_x[S_LEN * DIM];        // tf32-rounded x
__device__ float g_wq[DIM * DIM];         // tf32-rounded weights
__device__ float g_wk[DIM * DIM];
__device__ float g_wv[DIM * DIM];
__device__ float g_wo[DIM * DIM];

// ---------------------------------------------------------------------------
// helpers
// ---------------------------------------------------------------------------
__device__ __forceinline__ uint32_t f2tf(float x) {
    uint32_t u;
    asm("cvt.rna.tf32.f32 %0, %1;" : "=r"(u) : "f"(x));
    return u;
}

__device__ __forceinline__ void mma8(
    float& c0, float& c1, float& c2, float& c3,
    uint32_t a0, uint32_t a1, uint32_t a2, uint32_t a3,
    uint32_t b0, uint32_t b1)
{
    asm volatile(
        "mma.sync.aligned.m16n8k8.row.col.f32.tf32.tf32.f32 "
        "{%0,%1,%2,%3}, {%4,%5,%6,%7}, {%8,%9}, {%0,%1,%2,%3};\n"
        : "+f"(c0), "+f"(c1), "+f"(c2), "+f"(c3)
        : "r"(a0), "r"(a1), "r"(a2), "r"(a3), "r"(b0), "r"(b1));
}

__device__ __forceinline__ void cp16(uint32_t dst_smem, const void* src, int srcsz) {
    asm volatile("cp.async.ca.shared.global [%0], [%1], 16, %2;\n"
                 :: "r"(dst_smem), "l"(src), "r"(srcsz));
}
#define CP_COMMIT() asm volatile("cp.async.commit_group;\n")
#define CP_WAIT0()  asm volatile("cp.async.wait_group 0;\n")
#define CP_WAIT1()  asm volatile("cp.async.wait_group 1;\n")

__device__ __forceinline__ uint32_t smem_u32(const void* p) {
    return (uint32_t)__cvta_generic_to_shared(p);
}

// ---------------------------------------------------------------------------
// pre-round: out[i] = tf32_rna(in[i])
// ---------------------------------------------------------------------------
__global__ __launch_bounds__(256) void pre_round(
    const float* __restrict__ in, float* __restrict__ out, int n4)
{
    int i = blockIdx.x * 256 + threadIdx.x;
    if (i < n4) {
        float4 v = ((const float4*)in)[i];
        float4 r;
        r.x = __uint_as_float(f2tf(v.x));
        r.y = __uint_as_float(f2tf(v.y));
        r.z = __uint_as_float(f2tf(v.z));
        r.w = __uint_as_float(f2tf(v.w));
        ((float4*)out)[i] = r;
    }
}

// ---------------------------------------------------------------------------
// tf32 GEMM with cp.async 2-stage pipeline (verified R8 version).
// ---------------------------------------------------------------------------
#define GBK 16
#define GAS 20

__global__ __launch_bounds__(256, 2) void gemm_nt_tf32(
    const float* __restrict__ A,
    const float* __restrict__ w0, const float* __restrict__ w1, const float* __restrict__ w2,
    const float* __restrict__ b0p, const float* __restrict__ b1p, const float* __restrict__ b2p,
    float* __restrict__ c0p, float* __restrict__ c1p, float* __restrict__ c2p,
    int M, int N, int K, int round_out)
{
    __shared__ uint32_t As[2][128 * GAS];
    __shared__ uint32_t Bs[2][128 * GAS];

    const int z = blockIdx.z;
    const float* Bw   = (z == 0) ? w0 : (z == 1) ? w1 : w2;
    const float* bias = (z == 0) ? b0p : (z == 1) ? b1p : b2p;
    float* C          = (z == 0) ? c0p : (z == 1) ? c1p : c2p;

    const int tid = threadIdx.x;
    const int lane = tid & 31;
    const int wid = tid >> 5;
    const int bm = blockIdx.y * 128;
    const int bn = blockIdx.x * 128;
    const int warp_m = (wid >> 2) * 64;
    const int warp_n = (wid & 3) * 32;

    float acc[4][4][4];
#pragma unroll
    for (int a = 0; a < 4; a++)
#pragma unroll
        for (int b = 0; b < 4; b++)
#pragma unroll
            for (int c = 0; c < 4; c++) acc[a][b][c] = 0.f;

    const int r0s = tid >> 2;
    const int q0s = (tid & 3) * 4;
    const int r1s = (tid + 256) >> 2;
    const int q1s = q0s;

    auto issue = [&](int st, int kt) {
        int a0sz = (bm + r0s) < M ? 16 : 0;
        int a1sz = (bm + r1s) < M ? 16 : 0;
        cp16(smem_u32(&As[st][r0s * GAS + q0s]), A + (size_t)(bm + r0s) * K + kt + q0s, a0sz);
        cp16(smem_u32(&As[st][r1s * GAS + q1s]), A + (size_t)(bm + r1s) * K + kt + q1s, a1sz);
        cp16(smem_u32(&Bs[st][r0s * GAS + q0s]), Bw + (size_t)(bn + r0s) * K + kt + q0s, 16);
        cp16(smem_u32(&Bs[st][r1s * GAS + q1s]), Bw + (size_t)(bn + r1s) * K + kt + q1s, 16);
    };

    issue(0, 0);
    CP_COMMIT();

    int st = 0;
    for (int kt = 0; kt < K; kt += GBK, st ^= 1) {
        CP_WAIT0();
        __syncthreads();
        if (kt + GBK < K) {
            issue(st ^ 1, kt + GBK);
            CP_COMMIT();
        }

#pragma unroll
        for (int ks = 0; ks < 2; ks++) {
            const int c = ks * 8 + (lane & 3);
            uint32_t af[4][4];
#pragma unroll
            for (int mt = 0; mt < 4; mt++) {
                int row = warp_m + mt * 16 + (lane >> 2);
                af[mt][0] = As[st][row * GAS + c];
                af[mt][1] = As[st][(row + 8) * GAS + c];
                af[mt][2] = As[st][row * GAS + c + 4];
                af[mt][3] = As[st][(row + 8) * GAS + c + 4];
            }
            uint32_t bf[4][2];
#pragma unroll
            for (int nt = 0; nt < 4; nt++) {
                int n = warp_n + nt * 8 + (lane >> 2);
                bf[nt][0] = Bs[st][n * GAS + c];
                bf[nt][1] = Bs[st][n * GAS + c + 4];
            }
#pragma unroll
            for (int mt = 0; mt < 4; mt++)
#pragma unroll
                for (int nt = 0; nt < 4; nt++)
                    mma8(acc[mt][nt][0], acc[mt][nt][1], acc[mt][nt][2], acc[mt][nt][3],
                         af[mt][0], af[mt][1], af[mt][2], af[mt][3],
                         bf[nt][0], bf[nt][1]);
        }
        __syncthreads();
    }

#pragma unroll
    for (int mt = 0; mt < 4; mt++) {
        int row0 = bm + warp_m + mt * 16 + (lane >> 2);
#pragma unroll
        for (int nt = 0; nt < 4; nt++) {
            int col = bn + warp_n + nt * 8 + (lane & 3) * 2;
            float bb0 = bias[col], bb1 = bias[col + 1];
            float e00 = acc[mt][nt][0] + bb0, e01 = acc[mt][nt][1] + bb1;
            float e10 = acc[mt][nt][2] + bb0, e11 = acc[mt][nt][3] + bb1;
            if (round_out) {
                e00 = __uint_as_float(f2tf(e00));
                e01 = __uint_as_float(f2tf(e01));
                e10 = __uint_as_float(f2tf(e10));
                e11 = __uint_as_float(f2tf(e11));
            }
            if (row0 < M)
                *(float2*)(C + (size_t)row0 * N + col) = make_float2(e00, e01);
            if (row0 + 8 < M)
                *(float2*)(C + (size_t)(row0 + 8) * N + col) = make_float2(e10, e11);
        }
    }
}

// ---------------------------------------------------------------------------
// Fused RMSNorm + 3D RoPE (angles fp64, first principles), tf32-rounded store.
// ---------------------------------------------------------------------------
__global__ __launch_bounds__(256) void rmsrope_kernel(
    float* __restrict__ q, float* __restrict__ k,
    const float* __restrict__ gq, const float* __restrict__ gk)
{
    const int s = blockIdx.x;
    const int tid = threadIdx.x;
    float* qr = q + (size_t)s * DIM;
    float* kr = k + (size_t)s * DIM;

    float sq = 0.f, sk = 0.f;
    for (int i = tid; i < DIM; i += 256) {
        float a = qr[i]; sq = fmaf(a, a, sq);
        float b = kr[i]; sk = fmaf(b, b, sk);
    }
    __shared__ float bq_[256], bk_[256];
    bq_[tid] = sq; bk_[tid] = sk;
    __syncthreads();
    for (int off = 128; off > 0; off >>= 1) {
        if (tid < off) { bq_[tid] += bq_[tid + off]; bk_[tid] += bk_[tid + off]; }
        __syncthreads();
    }
    const float rq = rsqrtf(bq_[0] * (1.0f / DIM) + EPSN);
    const float rk = rsqrtf(bk_[0] * (1.0f / DIM) + EPSN);

    const int f = s / (HH * WW);
    const int rem = s - f * (HH * WW);
    const int hp = rem / WW;
    const int wp = rem - hp * WW;

#pragma unroll
    for (int u = 0; u < 3; u++) {
        int p = tid + u * 256;
        int h = p >> 6;
        int c = p & 63;
        int pos, j, dim;
        if (c < 22)      { pos = f;  j = c;      dim = 44; }
        else if (c < 43) { pos = hp; j = c - 22; dim = 42; }
        else             { pos = wp; j = c - 43; dim = 42; }
        double inv = pow(10000.0, -2.0 * (double)j / (double)dim);
        double ang = (double)pos * inv;
        double sd, cd;
        sincos(ang, &sd, &cd);
        float cs = (float)cd, sn = (float)sd;

        int base = h * HD + 2 * c;
        float q0 = qr[base] * rq * gq[base];
        float q1 = qr[base + 1] * rq * gq[base + 1];
        qr[base]     = __uint_as_float(f2tf(q0 * cs - q1 * sn));
        qr[base + 1] = __uint_as_float(f2tf(q0 * sn + q1 * cs));
        float k0 = kr[base] * rk * gk[base];
        float k1 = kr[base + 1] * rk * gk[base + 1];
        kr[base]     = __uint_as_float(f2tf(k0 * cs - k1 * sn));
        kr[base + 1] = __uint_as_float(f2tf(k0 * sn + k1 * cs));
    }
}

// ---------------------------------------------------------------------------
// Flash attention v2: Q-fragments in registers, cp.async double-buffered K/V,
// permuted P layout (LDS.64 A-fragments in O-phase), vectorized softmax.
// 64 q-rows/block, 256 threads, 1 CTA/SM.
// ---------------------------------------------------------------------------
#define QT 64
#define KVS 132
#define PSS 72
#define SM_K(s) ((s) * QT * KVS)
#define SM_V(s) (2 * QT * KVS + (s) * QT * KVS)
#define SM_P    (4 * QT * KVS)
#define SM_RED  (SM_P + QT * PSS)
#define FL_U32  (SM_RED + 3 * QT)
#define FL_SMEM_BYTES (FL_U32 * 4)

__global__ __launch_bounds__(256, 1) void flash_tf32(
    const float* __restrict__ q, const float* __restrict__ k,
    const float* __restrict__ v, float* __restrict__ o,
    const int* __restrict__ seq_lens)
{
    extern __shared__ uint32_t smu[];
    float* Ps   = (float*)(smu + SM_P);
    float* mrow = (float*)(smu + SM_RED);
    float* lrow = mrow + QT;
    float* arow = lrow + QT;
    const uint32_t sbase = smem_u32(smu);

    const int tid = threadIdx.x;
    const int lane = tid & 31;
    const int wid = tid >> 5;
    const int g = lane >> 2;
    const int t = lane & 3;
    const int head = blockIdx.y;
    const int q0 = blockIdx.x * QT;
    const int seqlen = seq_lens[0];
    const int hoff = head * HD;
    const int nch = (seqlen + 63) >> 6;

    // S-phase: 4m x 2n (warp tile 16x32). O-phase: 2m x 4n (warp tile 32x32).
    const int wm_s = (wid >> 1) * 16;
    const int wn_s = (wid & 1) * 32;
    const int wm_o = (wid >> 2) * 32;
    const int wn_o = (wid & 3) * 32;

    // cp.async K/V tile issue: 2048 float4 slots per tile, 8 per thread each
    auto issue = [&](int s, int c) {
        int kv0 = c * 64;
#pragma unroll
        for (int u = 0; u < 8; u++) {
            int slot = tid + 256 * u;
            int r = slot >> 5;
            int qq = (slot & 31) * 4;
            int gr = kv0 + r;
            int sz = (gr < seqlen) ? 16 : 0;
            cp16(sbase + (SM_K(s) + r * KVS + qq) * 4,
                 k + (size_t)gr * DIM + hoff + qq, sz);
            cp16(sbase + (SM_V(s) + r * KVS + qq) * 4,
                 v + (size_t)gr * DIM + hoff + qq, sz);
        }
    };

    issue(0, 0); CP_COMMIT();
    if (nch > 1) { issue(1, 1); CP_COMMIT(); }

    // Q fragments in registers (loop-invariant). 64 regs.
    float qf[16][4];
    {
        int r0 = q0 + wm_s + g;
        const float* qp0 = q + (size_t)r0 * DIM + hoff;
        const float* qp1 = qp0 + (size_t)8 * DIM;
        bool v0 = r0 < S_LEN, v1 = (r0 + 8) < S_LEN;
#pragma unroll
        for (int ks = 0; ks < 16; ks++) {
            int c = ks * 8 + t;
            qf[ks][0] = v0 ? qp0[c] : 0.f;
            qf[ks][1] = v1 ? qp1[c] : 0.f;
            qf[ks][2] = v0 ? qp0[c + 4] : 0.f;
            qf[ks][3] = v1 ? qp1[c + 4] : 0.f;
        }
    }
    if (tid < QT) { mrow[tid] = -3.0e38f; lrow[tid] = 0.f; }

    float oacc[2][4][4];
#pragma unroll
    for (int a = 0; a < 2; a++)
#pragma unroll
        for (int b = 0; b < 4; b++)
#pragma unroll
            for (int c = 0; c < 4; c++) oacc[a][b][c] = 0.f;

    const float scale = 0.08838834764831845f;
    // permuted P column offsets: col b in 8-group stored at 2b (b<4) / 2(b-4)+1
    const int off0 = (t < 2) ? 4 * t : 4 * t - 7;       // for col = 2t
    const int off1 = (t < 2) ? 4 * t + 2 : 4 * t - 5;   // for col = 2t+1

    for (int c = 0; c < nch; c++) {
        const int s = c & 1;
        const int kv0 = c * 64;
        if (c + 1 < nch) { CP_WAIT1(); } else { CP_WAIT0(); }
        __syncthreads();
        const uint32_t* Kt = smu + SM_K(s);
        const uint32_t* Vt = smu + SM_V(s);

        // ---------- S = Q @ K^T : per-warp 16x32, A from registers ----------
        float sacc[4][4];
#pragma unroll
        for (int a = 0; a < 4; a++)
#pragma unroll
            for (int b = 0; b < 4; b++) sacc[a][b] = 0.f;

#pragma unroll
        for (int ks = 0; ks < 16; ks++) {
            const int cc = ks * 8 + t;
            uint32_t a0 = __float_as_uint(qf[ks][0]);
            uint32_t a1 = __float_as_uint(qf[ks][1]);
            uint32_t a2 = __float_as_uint(qf[ks][2]);
            uint32_t a3 = __float_as_uint(qf[ks][3]);
            uint32_t b0[4], b1[4];
#pragma unroll
            for (int nt = 0; nt < 4; nt++) {
                int n = wn_s + nt * 8 + g;
                b0[nt] = Kt[n * KVS + cc];
                b1[nt] = Kt[n * KVS + cc + 4];
            }
#pragma unroll
            for (int nt = 0; nt < 4; nt++)
                mma8(sacc[nt][0], sacc[nt][1], sacc[nt][2], sacc[nt][3],
                     a0, a1, a2, a3, b0[nt], b1[nt]);
        }

        // write scaled+masked scores to permuted P
        {
            int row = wm_s + g;
#pragma unroll
            for (int nt = 0; nt < 4; nt++) {
                int base = wn_s + nt * 8;
                int col = base + 2 * t;
                bool m0 = (kv0 + col) >= seqlen;
                bool m1 = (kv0 + col + 1) >= seqlen;
                Ps[row * PSS + base + off0]       = m0 ? -1e30f : sacc[nt][0] * scale;
                Ps[row * PSS + base + off1]       = m1 ? -1e30f : sacc[nt][1] * scale;
                Ps[(row + 8) * PSS + base + off0] = m0 ? -1e30f : sacc[nt][2] * scale;
                Ps[(row + 8) * PSS + base + off1] = m1 ? -1e30f : sacc[nt][3] * scale;
            }
        }
        __syncthreads();

        // ---------- online softmax (4 threads/row, float4) ----------
        {
            const int i = tid >> 2, sub = tid & 3;
            float* prow = Ps + i * PSS + sub * 16;
            float4 pv[4];
            float mold = mrow[i];
            float mloc = -3.0e38f;
#pragma unroll
            for (int j = 0; j < 4; j++) {
                pv[j] = *(float4*)(prow + 4 * j);
                mloc = fmaxf(mloc, fmaxf(fmaxf(pv[j].x, pv[j].y), fmaxf(pv[j].z, pv[j].w)));
            }
            mloc = fmaxf(mloc, __shfl_xor_sync(0xffffffffu, mloc, 1));
            mloc = fmaxf(mloc, __shfl_xor_sync(0xffffffffu, mloc, 2));
            float mnew = fmaxf(mold, mloc);
            float sum = 0.f;
#pragma unroll
            for (int j = 0; j < 4; j++) {
                pv[j].x = __expf(pv[j].x - mnew);
                pv[j].y = __expf(pv[j].y - mnew);
                pv[j].z = __expf(pv[j].z - mnew);
                pv[j].w = __expf(pv[j].w - mnew);
                sum += pv[j].x + pv[j].y + pv[j].z + pv[j].w;
                *(float4*)(prow + 4 * j) = pv[j];
            }
            sum += __shfl_xor_sync(0xffffffffu, sum, 1);
            sum += __shfl_xor_sync(0xffffffffu, sum, 2);
            if (sub == 0) {
                float al = __expf(mold - mnew);
                arow[i] = al;
                lrow[i] = lrow[i] * al + sum;
                mrow[i] = mnew;
            }
        }
        __syncthreads();

        // ---------- O = alpha*O + P @ V : per-warp 32x32 ----------
#pragma unroll
        for (int mt = 0; mt < 2; mt++) {
            int row = wm_o + mt * 16 + g;
            float al0 = arow[row];
            float al1 = arow[row + 8];
#pragma unroll
            for (int nt = 0; nt < 4; nt++) {
                oacc[mt][nt][0] *= al0;
                oacc[mt][nt][1] *= al0;
                oacc[mt][nt][2] *= al1;
                oacc[mt][nt][3] *= al1;
            }
        }
#pragma unroll
        for (int ks = 0; ks < 8; ks++) {
            const int cc = ks * 8 + t;
            uint32_t a[2][4];
#pragma unroll
            for (int mt = 0; mt < 2; mt++) {
                int row = wm_o + mt * 16 + g;
                float2 p0 = *(float2*)(Ps + row * PSS + ks * 8 + 2 * t);
                float2 p1 = *(float2*)(Ps + (row + 8) * PSS + ks * 8 + 2 * t);
                a[mt][0] = __float_as_uint(p0.x);
                a[mt][1] = __float_as_uint(p1.x);
                a[mt][2] = __float_as_uint(p0.y);
                a[mt][3] = __float_as_uint(p1.y);
            }
#pragma unroll
            for (int nt = 0; nt < 4; nt++) {
                int n = wn_o + nt * 8 + g;
                uint32_t vb0 = Vt[cc * KVS + n];
                uint32_t vb1 = Vt[(cc + 4) * KVS + n];
#pragma unroll
                for (int mt = 0; mt < 2; mt++)
                    mma8(oacc[mt][nt][0], oacc[mt][nt][1], oacc[mt][nt][2], oacc[mt][nt][3],
                         a[mt][0], a[mt][1], a[mt][2], a[mt][3], vb0, vb1);
            }
        }
        __syncthreads();   // stage s fully consumed
        if (c + 2 < nch) { issue(s, c + 2); CP_COMMIT(); }
    }

    // epilogue: divide by l, tf32-round, store
#pragma unroll
    for (int mt = 0; mt < 2; mt++) {
        int lr0 = wm_o + mt * 16 + g;
        int grow0 = q0 + lr0;
        float inv0 = 1.0f / lrow[lr0];
        float inv1 = 1.0f / lrow[lr0 + 8];
#pragma unroll
        for (int nt = 0; nt < 4; nt++) {
            int col = hoff + wn_o + nt * 8 + t * 2;
            if (grow0 < S_LEN) {
                float2 v0 = make_float2(
                    __uint_as_float(f2tf(oacc[mt][nt][0] * inv0)),
                    __uint_as_float(f2tf(oacc[mt][nt][1] * inv0)));
                *(float2*)(o + (size_t)grow0 * DIM + col) = v0;
            }
            if (grow0 + 8 < S_LEN) {
                float2 v1 = make_float2(
                    __uint_as_float(f2tf(oacc[mt][nt][2] * inv1)),
                    __uint_as_float(f2tf(oacc[mt][nt][3] * inv1)));
                *(float2*)(o + (size_t)(grow0 + 8) * DIM + col) = v1;
            }
        }
    }
}

// ---------------------------------------------------------------------------
extern "C" void kernel_launch(void* const* d_in, const int* in_sizes, int n_in,
                              void* d_out, int out_size)
{
    const float* x  = (const float*)d_in[0];
    const float* wq = (const float*)d_in[1];
    const float* bq = (const float*)d_in[2];
    const float* wk = (const float*)d_in[3];
    const float* bk = (const float*)d_in[4];
    const float* wv = (const float*)d_in[5];
    const float* bv = (const float*)d_in[6];
    const float* wo = (const float*)d_in[7];
    const float* bo = (const float*)d_in[8];
    const float* gq = (const float*)d_in[9];
    const float* gk = (const float*)d_in[10];
    const int* seq_lens = (const int*)d_in[12];
    float* out = (float*)d_out;

    float *qp, *kp, *vp, *op, *xp, *wqp, *wkp, *wvp, *wop;
    cudaGetSymbolAddress((void**)&qp, g_q);
    cudaGetSymbolAddress((void**)&kp, g_k);
    cudaGetSymbolAddress((void**)&vp, g_v);
    cudaGetSymbolAddress((void**)&op, g_o);
    cudaGetSymbolAddress((void**)&xp, g_x);
    cudaGetSymbolAddress((void**)&wqp, g_wq);
    cudaGetSymbolAddress((void**)&wkp, g_wk);
    cudaGetSymbolAddress((void**)&wvp, g_wv);
    cudaGetSymbolAddress((void**)&wop, g_wo);

    const int nx4 = S_LEN * DIM / 4;
    const int nw4 = DIM * DIM / 4;
    pre_round<<<(nx4 + 255) / 256, 256>>>(x, xp, nx4);
    pre_round<<<(nw4 + 255) / 256, 256>>>(wq, wqp, nw4);
    pre_round<<<(nw4 + 255) / 256, 256>>>(wk, wkp, nw4);
    pre_round<<<(nw4 + 255) / 256, 256>>>(wv, wvp, nw4);
    pre_round<<<(nw4 + 255) / 256, 256>>>(wo, wop, nw4);

    // fused Q/K/V projections (tf32-rounded outputs)
    dim3 gqkv(DIM / 128, (S_LEN + 127) / 128, 3);
    gemm_nt_tf32<<<gqkv, 256>>>(xp, wqp, wkp, wvp, bq, bk, bv, qp, kp, vp,
                                S_LEN, DIM, DIM, 1);

    rmsrope_kernel<<<S_LEN, 256>>>(qp, kp, gq, gk);

    cudaFuncSetAttribute(flash_tf32, cudaFuncAttributeMaxDynamicSharedMemorySize,
                         FL_SMEM_BYTES);
    flash_tf32<<<dim3((S_LEN + QT - 1) / QT, NH), 256, FL_SMEM_BYTES>>>(
        qp, kp, vp, op, seq_lens);

    // output projection (fp32 output)
    dim3 go(DIM / 128, (S_LEN + 127) / 128, 1);
    gemm_nt_tf32<<<go, 256>>>(op, wop, wop, wop, bo, bo, bo, out, out, out,
                              S_LEN, DIM, DIM, 0);
}

// round 11
// speedup vs baseline: 1.8779x; 1.8779x over previous
#include <cuda_runtime.h>
#include <math.h>
#include <stdint.h>

#define S_LEN 3744
#define DIM 1536
#define NH 12
#define HD 128
#define HH 26
#define WW 48
#define EPSN 1e-6f

// scratch (allocation-free rule: __device__ globals)
__device__ float g_q[S_LEN * DIM];
__device__ float g_k[S_LEN * DIM];
__device__ float g_v[S_LEN * DIM];
__device__ float g_o[S_LEN * DIM];
__device__ float g_x[S_LEN * DIM];        // tf32-rounded x
__device__ float g_wq[DIM * DIM];         // tf32-rounded weights
__device__ float g_wk[DIM * DIM];
__device__ float g_wv[DIM * DIM];
__device__ float g_wo[DIM * DIM];

// ---------------------------------------------------------------------------
// helpers
// ---------------------------------------------------------------------------
__device__ __forceinline__ uint32_t f2tf(float x) {
    uint32_t u;
    asm("cvt.rna.tf32.f32 %0, %1;" : "=r"(u) : "f"(x));
    return u;
}

__device__ __forceinline__ void mma8(
    float& c0, float& c1, float& c2, float& c3,
    uint32_t a0, uint32_t a1, uint32_t a2, uint32_t a3,
    uint32_t b0, uint32_t b1)
{
    asm volatile(
        "mma.sync.aligned.m16n8k8.row.col.f32.tf32.tf32.f32 "
        "{%0,%1,%2,%3}, {%4,%5,%6,%7}, {%8,%9}, {%0,%1,%2,%3};\n"
        : "+f"(c0), "+f"(c1), "+f"(c2), "+f"(c3)
        : "r"(a0), "r"(a1), "r"(a2), "r"(a3), "r"(b0), "r"(b1));
}

__device__ __forceinline__ void cp16(uint32_t dst_smem, const void* src, int srcsz) {
    asm volatile("cp.async.ca.shared.global [%0], [%1], 16, %2;\n"
                 :: "r"(dst_smem), "l"(src), "r"(srcsz));
}
#define CP_COMMIT() asm volatile("cp.async.commit_group;\n")
#define CP_WAIT0()  asm volatile("cp.async.wait_group 0;\n")

__device__ __forceinline__ uint32_t smem_u32(const void* p) {
    return (uint32_t)__cvta_generic_to_shared(p);
}

// ---------------------------------------------------------------------------
// fused pre-round: 5 tensors, flattened linear index, tf32_rna
// ---------------------------------------------------------------------------
#define NX4 (S_LEN * DIM / 4)
#define NW4 (DIM * DIM / 4)

__global__ __launch_bounds__(256) void pre_round5(
    const float* __restrict__ x,  float* __restrict__ xo,
    const float* __restrict__ w0, float* __restrict__ w0o,
    const float* __restrict__ w1, float* __restrict__ w1o,
    const float* __restrict__ w2, float* __restrict__ w2o,
    const float* __restrict__ w3, float* __restrict__ w3o)
{
    int i = blockIdx.x * 256 + threadIdx.x;
    const float* in; float* out; int j;
    if (i < NX4)                { in = x;  out = xo;  j = i; }
    else if ((i -= NX4) < NW4)  { in = w0; out = w0o; j = i; }
    else if ((i -= NW4) < NW4)  { in = w1; out = w1o; j = i; }
    else if ((i -= NW4) < NW4)  { in = w2; out = w2o; j = i; }
    else if ((i -= NW4) < NW4)  { in = w3; out = w3o; j = i; }
    else return;
    float4 v = ((const float4*)in)[j];
    float4 r;
    r.x = __uint_as_float(f2tf(v.x));
    r.y = __uint_as_float(f2tf(v.y));
    r.z = __uint_as_float(f2tf(v.z));
    r.w = __uint_as_float(f2tf(v.w));
    ((float4*)out)[j] = r;
}
#define PR_TOTAL (NX4 + 4 * NW4)

// ---------------------------------------------------------------------------
// tf32 GEMM, cp.async 2-stage, 128x128 block, 128 threads (4 warps of 64x64).
// C_z[M,N] = A[M,K] @ W_z[N,K]^T + bias_z[N]
// ---------------------------------------------------------------------------
#define GBK 16
#define GAS 20

__global__ __launch_bounds__(128) void gemm_nt_tf32(
    const float* __restrict__ A,
    const float* __restrict__ w0, const float* __restrict__ w1, const float* __restrict__ w2,
    const float* __restrict__ b0p, const float* __restrict__ b1p, const float* __restrict__ b2p,
    float* __restrict__ c0p, float* __restrict__ c1p, float* __restrict__ c2p,
    int M, int N, int K, int round_out)
{
    __shared__ uint32_t As[2][128 * GAS];
    __shared__ uint32_t Bs[2][128 * GAS];

    const int z = blockIdx.z;
    const float* Bw   = (z == 0) ? w0 : (z == 1) ? w1 : w2;
    const float* bias = (z == 0) ? b0p : (z == 1) ? b1p : b2p;
    float* C          = (z == 0) ? c0p : (z == 1) ? c1p : c2p;

    const int tid = threadIdx.x;
    const int lane = tid & 31;
    const int wid = tid >> 5;          // 0..3
    const int g = lane >> 2;
    const int t = lane & 3;
    const int bm = blockIdx.y * 128;
    const int bn = blockIdx.x * 128;
    const int warp_m = (wid >> 1) * 64;
    const int warp_n = (wid & 1) * 64;

    float acc[4][8][4];
#pragma unroll
    for (int a = 0; a < 4; a++)
#pragma unroll
        for (int b = 0; b < 8; b++)
#pragma unroll
            for (int c = 0; c < 4; c++) acc[a][b][c] = 0.f;

    // cp.async: 512 16B slots per matrix tile, 128 threads -> 4 each
    auto issue = [&](int st, int kt) {
#pragma unroll
        for (int u = 0; u < 4; u++) {
            int slot = tid + 128 * u;
            int r = slot >> 2;
            int q = (slot & 3) * 4;
            int asz = (bm + r) < M ? 16 : 0;
            cp16(smem_u32(&As[st][r * GAS + q]), A + (size_t)(bm + r) * K + kt + q, asz);
            cp16(smem_u32(&Bs[st][r * GAS + q]), Bw + (size_t)(bn + r) * K + kt + q, 16);
        }
    };

    issue(0, 0);
    CP_COMMIT();

    int st = 0;
    for (int kt = 0; kt < K; kt += GBK, st ^= 1) {
        CP_WAIT0();
        __syncthreads();
        if (kt + GBK < K) {
            issue(st ^ 1, kt + GBK);
            CP_COMMIT();
        }

#pragma unroll
        for (int ks = 0; ks < 2; ks++) {
            const int c = ks * 8 + t;
            uint32_t af[4][4];
#pragma unroll
            for (int mt = 0; mt < 4; mt++) {
                int row = warp_m + mt * 16 + g;
                af[mt][0] = As[st][row * GAS + c];
                af[mt][1] = As[st][(row + 8) * GAS + c];
                af[mt][2] = As[st][row * GAS + c + 4];
                af[mt][3] = As[st][(row + 8) * GAS + c + 4];
            }
            uint32_t bf[8][2];
#pragma unroll
            for (int nt = 0; nt < 8; nt++) {
                int n = warp_n + nt * 8 + g;
                bf[nt][0] = Bs[st][n * GAS + c];
                bf[nt][1] = Bs[st][n * GAS + c + 4];
            }
#pragma unroll
            for (int mt = 0; mt < 4; mt++)
#pragma unroll
                for (int nt = 0; nt < 8; nt++)
                    mma8(acc[mt][nt][0], acc[mt][nt][1], acc[mt][nt][2], acc[mt][nt][3],
                         af[mt][0], af[mt][1], af[mt][2], af[mt][3],
                         bf[nt][0], bf[nt][1]);
        }
        __syncthreads();
    }

#pragma unroll
    for (int mt = 0; mt < 4; mt++) {
        int row0 = bm + warp_m + mt * 16 + g;
#pragma unroll
        for (int nt = 0; nt < 8; nt++) {
            int col = bn + warp_n + nt * 8 + t * 2;
            float bb0 = bias[col], bb1 = bias[col + 1];
            float e00 = acc[mt][nt][0] + bb0, e01 = acc[mt][nt][1] + bb1;
            float e10 = acc[mt][nt][2] + bb0, e11 = acc[mt][nt][3] + bb1;
            if (round_out) {
                e00 = __uint_as_float(f2tf(e00));
                e01 = __uint_as_float(f2tf(e01));
                e10 = __uint_as_float(f2tf(e10));
                e11 = __uint_as_float(f2tf(e11));
            }
            if (row0 < M)
                *(float2*)(C + (size_t)row0 * N + col) = make_float2(e00, e01);
            if (row0 + 8 < M)
                *(float2*)(C + (size_t)(row0 + 8) * N + col) = make_float2(e10, e11);
        }
    }
}

// ---------------------------------------------------------------------------
// Fused RMSNorm + 3D RoPE (angles fp64, first principles), tf32-rounded store.
// ---------------------------------------------------------------------------
__global__ __launch_bounds__(256) void rmsrope_kernel(
    float* __restrict__ q, float* __restrict__ k,
    const float* __restrict__ gq, const float* __restrict__ gk)
{
    const int s = blockIdx.x;
    const int tid = threadIdx.x;
    float* qr = q + (size_t)s * DIM;
    float* kr = k + (size_t)s * DIM;

    float sq = 0.f, sk = 0.f;
    for (int i = tid; i < DIM; i += 256) {
        float a = qr[i]; sq = fmaf(a, a, sq);
        float b = kr[i]; sk = fmaf(b, b, sk);
    }
    __shared__ float bq_[256], bk_[256];
    bq_[tid] = sq; bk_[tid] = sk;
    __syncthreads();
    for (int off = 128; off > 0; off >>= 1) {
        if (tid < off) { bq_[tid] += bq_[tid + off]; bk_[tid] += bk_[tid + off]; }
        __syncthreads();
    }
    const float rq = rsqrtf(bq_[0] * (1.0f / DIM) + EPSN);
    const float rk = rsqrtf(bk_[0] * (1.0f / DIM) + EPSN);

    const int f = s / (HH * WW);
    const int rem = s - f * (HH * WW);
    const int hp = rem / WW;
    const int wp = rem - hp * WW;

#pragma unroll
    for (int u = 0; u < 3; u++) {
        int p = tid + u * 256;
        int h = p >> 6;
        int c = p & 63;
        int pos, j, dim;
        if (c < 22)      { pos = f;  j = c;      dim = 44; }
        else if (c < 43) { pos = hp; j = c - 22; dim = 42; }
        else             { pos = wp; j = c - 43; dim = 42; }
        double inv = pow(10000.0, -2.0 * (double)j / (double)dim);
        double ang = (double)pos * inv;
        double sd, cd;
        sincos(ang, &sd, &cd);
        float cs = (float)cd, sn = (float)sd;

        int base = h * HD + 2 * c;
        float q0 = qr[base] * rq * gq[base];
        float q1 = qr[base + 1] * rq * gq[base + 1];
        qr[base]     = __uint_as_float(f2tf(q0 * cs - q1 * sn));
        qr[base + 1] = __uint_as_float(f2tf(q0 * sn + q1 * cs));
        float k0 = kr[base] * rk * gk[base];
        float k1 = kr[base + 1] * rk * gk[base + 1];
        kr[base]     = __uint_as_float(f2tf(k0 * cs - k1 * sn));
        kr[base + 1] = __uint_as_float(f2tf(k0 * sn + k1 * cs));
    }
}

// ---------------------------------------------------------------------------
// Flash attention (exact R8 version: 64 q-rows/block, 256 threads, 2 CTA/SM,
// shared K/V smem tile, register-prefetched KV).
// ---------------------------------------------------------------------------
#define QT 64
#define QKS 132
#define PSS 68
#define FL_SMEM_U32 (2 * QT * QKS + QT * PSS + 3 * QT)
#define FL_SMEM_BYTES (FL_SMEM_U32 * 4)

__global__ __launch_bounds__(256, 2) void flash_tf32(
    const float* __restrict__ q, const float* __restrict__ k,
    const float* __restrict__ v, float* __restrict__ o,
    const int* __restrict__ seq_lens)
{
    extern __shared__ uint32_t smu[];
    uint32_t* Qs  = smu;
    uint32_t* KVs = Qs + QT * QKS;
    float* Ps   = (float*)(KVs + QT * QKS);
    float* mrow = Ps + QT * PSS;
    float* lrow = mrow + QT;
    float* arow = lrow + QT;

    const int tid = threadIdx.x;
    const int lane = tid & 31;
    const int wid = tid >> 5;
    const int head = blockIdx.y;
    const int q0 = blockIdx.x * QT;
    const int seqlen = seq_lens[0];
    const int hoff = head * HD;

    const int wm_s = (wid >> 2) * 32;
    const int wn_s = (wid & 3) * 16;
    const int wm_o = (wid >> 2) * 32;
    const int wn_o = (wid & 3) * 32;

#pragma unroll
    for (int u = 0; u < 8; u++) {
        int slot = tid + 256 * u;
        int r = slot >> 5;
        int qq = (slot & 31) * 4;
        int grow = q0 + r;
        float4 val = (grow < S_LEN) ? *(const float4*)(q + (size_t)grow * DIM + hoff + qq)
                                    : make_float4(0.f, 0.f, 0.f, 0.f);
        Qs[r * QKS + qq + 0] = __float_as_uint(val.x);
        Qs[r * QKS + qq + 1] = __float_as_uint(val.y);
        Qs[r * QKS + qq + 2] = __float_as_uint(val.z);
        Qs[r * QKS + qq + 3] = __float_as_uint(val.w);
    }
    if (tid < QT) { mrow[tid] = -3.0e38f; lrow[tid] = 0.f; }

    float oacc[2][4][4];
#pragma unroll
    for (int a = 0; a < 2; a++)
#pragma unroll
        for (int b = 0; b < 4; b++)
#pragma unroll
            for (int c = 0; c < 4; c++) oacc[a][b][c] = 0.f;

    const float scale = 0.08838834764831845f;

    const int ldr = tid >> 5;
    const int ldq = (tid & 31) * 4;

    float4 kvreg[8];
#pragma unroll
    for (int u = 0; u < 8; u++) {
        int r = ldr + u * 8;
        kvreg[u] = (r < seqlen) ? *(const float4*)(k + (size_t)r * DIM + hoff + ldq)
                                : make_float4(0.f, 0.f, 0.f, 0.f);
    }

    for (int kv0 = 0; kv0 < seqlen; kv0 += 64) {
        __syncthreads();
#pragma unroll
        for (int u = 0; u < 8; u++) {
            int r = ldr + u * 8;
            KVs[r * QKS + ldq + 0] = __float_as_uint(kvreg[u].x);
            KVs[r * QKS + ldq + 1] = __float_as_uint(kvreg[u].y);
            KVs[r * QKS + ldq + 2] = __float_as_uint(kvreg[u].z);
            KVs[r * QKS + ldq + 3] = __float_as_uint(kvreg[u].w);
        }
        __syncthreads();

#pragma unroll
        for (int u = 0; u < 8; u++) {
            int r = kv0 + ldr + u * 8;
            kvreg[u] = (r < seqlen) ? *(const float4*)(v + (size_t)r * DIM + hoff + ldq)
                                    : make_float4(0.f, 0.f, 0.f, 0.f);
        }

        float sacc[2][2][4];
#pragma unroll
        for (int a = 0; a < 2; a++)
#pragma unroll
            for (int b = 0; b < 2; b++)
#pragma unroll
                for (int c = 0; c < 4; c++) sacc[a][b][c] = 0.f;

#pragma unroll
        for (int ks = 0; ks < 16; ks++) {
            const int c = ks * 8 + (lane & 3);
            uint32_t af[2][4];
#pragma unroll
            for (int mt = 0; mt < 2; mt++) {
                int row = wm_s + mt * 16 + (lane >> 2);
                af[mt][0] = Qs[row * QKS + c];
                af[mt][1] = Qs[(row + 8) * QKS + c];
                af[mt][2] = Qs[row * QKS + c + 4];
                af[mt][3] = Qs[(row + 8) * QKS + c + 4];
            }
            uint32_t bf[2][2];
#pragma unroll
            for (int nt = 0; nt < 2; nt++) {
                int n = wn_s + nt * 8 + (lane >> 2);
                bf[nt][0] = KVs[n * QKS + c];
                bf[nt][1] = KVs[n * QKS + c + 4];
            }
#pragma unroll
            for (int mt = 0; mt < 2; mt++)
#pragma unroll
                for (int nt = 0; nt < 2; nt++)
                    mma8(sacc[mt][nt][0], sacc[mt][nt][1], sacc[mt][nt][2], sacc[mt][nt][3],
                         af[mt][0], af[mt][1], af[mt][2], af[mt][3],
                         bf[nt][0], bf[nt][1]);
        }

#pragma unroll
        for (int mt = 0; mt < 2; mt++) {
            int row = wm_s + mt * 16 + (lane >> 2);
#pragma unroll
            for (int nt = 0; nt < 2; nt++) {
                int col = wn_s + nt * 8 + (lane & 3) * 2;
                bool m0 = (kv0 + col) >= seqlen;
                bool m1 = (kv0 + col + 1) >= seqlen;
                float2 v0 = make_float2(m0 ? -1e30f : sacc[mt][nt][0] * scale,
                                        m1 ? -1e30f : sacc[mt][nt][1] * scale);
                float2 v1 = make_float2(m0 ? -1e30f : sacc[mt][nt][2] * scale,
                                        m1 ? -1e30f : sacc[mt][nt][3] * scale);
                *(float2*)(Ps + row * PSS + col) = v0;
                *(float2*)(Ps + (row + 8) * PSS + col) = v1;
            }
        }
        __syncthreads();

#pragma unroll
        for (int u = 0; u < 8; u++) {
            int r = ldr + u * 8;
            KVs[r * QKS + ldq + 0] = __float_as_uint(kvreg[u].x);
            KVs[r * QKS + ldq + 1] = __float_as_uint(kvreg[u].y);
            KVs[r * QKS + ldq + 2] = __float_as_uint(kvreg[u].z);
            KVs[r * QKS + ldq + 3] = __float_as_uint(kvreg[u].w);
        }

        if (kv0 + 64 < seqlen) {
#pragma unroll
            for (int u = 0; u < 8; u++) {
                int r = kv0 + 64 + ldr + u * 8;
                kvreg[u] = (r < seqlen) ? *(const float4*)(k + (size_t)r * DIM + hoff + ldq)
                                        : make_float4(0.f, 0.f, 0.f, 0.f);
            }
        }

        {
            const int i = tid >> 2, sub = tid & 3;
            const int jbase = sub * 16;
            float mold = mrow[i];
            float mloc = -3.0e38f;
#pragma unroll
            for (int jj = 0; jj < 16; jj++)
                mloc = fmaxf(mloc, Ps[i * PSS + jbase + jj]);
            mloc = fmaxf(mloc, __shfl_xor_sync(0xffffffffu, mloc, 1));
            mloc = fmaxf(mloc, __shfl_xor_sync(0xffffffffu, mloc, 2));
            float mnew = fmaxf(mold, mloc);
            float sum = 0.f;
#pragma unroll
            for (int jj = 0; jj < 16; jj++) {
                float p = __expf(Ps[i * PSS + jbase + jj] - mnew);
                Ps[i * PSS + jbase + jj] = p;
                sum += p;
            }
            sum += __shfl_xor_sync(0xffffffffu, sum, 1);
            sum += __shfl_xor_sync(0xffffffffu, sum, 2);
            if (sub == 0) {
                float al = __expf(mold - mnew);
                arow[i] = al;
                lrow[i] = lrow[i] * al + sum;
                mrow[i] = mnew;
            }
        }
        __syncthreads();

#pragma unroll
        for (int mt = 0; mt < 2; mt++) {
            int row = wm_o + mt * 16 + (lane >> 2);
            float al0 = arow[row];
            float al1 = arow[row + 8];
#pragma unroll
            for (int nt = 0; nt < 4; nt++) {
                oacc[mt][nt][0] *= al0;
                oacc[mt][nt][1] *= al0;
                oacc[mt][nt][2] *= al1;
                oacc[mt][nt][3] *= al1;
            }
        }
#pragma unroll
        for (int ks = 0; ks < 8; ks++) {
            const int c = ks * 8 + (lane & 3);
            uint32_t paf[2][4];
#pragma unroll
            for (int mt = 0; mt < 2; mt++) {
                int row = wm_o + mt * 16 + (lane >> 2);
                paf[mt][0] = __float_as_uint(Ps[row * PSS + c]);
                paf[mt][1] = __float_as_uint(Ps[(row + 8) * PSS + c]);
                paf[mt][2] = __float_as_uint(Ps[row * PSS + c + 4]);
                paf[mt][3] = __float_as_uint(Ps[(row + 8) * PSS + c + 4]);
            }
#pragma unroll
            for (int nt = 0; nt < 4; nt++) {
                int n = wn_o + nt * 8 + (lane >> 2);
                uint32_t b0 = KVs[c * QKS + n];
                uint32_t b1 = KVs[(c + 4) * QKS + n];
#pragma unroll
                for (int mt = 0; mt < 2; mt++)
                    mma8(oacc[mt][nt][0], oacc[mt][nt][1], oacc[mt][nt][2], oacc[mt][nt][3],
                         paf[mt][0], paf[mt][1], paf[mt][2], paf[mt][3], b0, b1);
            }
        }
    }

#pragma unroll
    for (int mt = 0; mt < 2; mt++) {
        int lrow0 = wm_o + mt * 16 + (lane >> 2);
        int grow0 = q0 + lrow0;
        float inv0 = 1.0f / lrow[lrow0];
        float inv1 = 1.0f / lrow[lrow0 + 8];
#pragma unroll
        for (int nt = 0; nt < 4; nt++) {
            int col = hoff + wn_o + nt * 8 + (lane & 3) * 2;
            if (grow0 < S_LEN) {
                float2 v0 = make_float2(
                    __uint_as_float(f2tf(oacc[mt][nt][0] * inv0)),
                    __uint_as_float(f2tf(oacc[mt][nt][1] * inv0)));
                *(float2*)(o + (size_t)grow0 * DIM + col) = v0;
            }
            if (grow0 + 8 < S_LEN) {
                float2 v1 = make_float2(
                    __uint_as_float(f2tf(oacc[mt][nt][2] * inv1)),
                    __uint_as_float(f2tf(oacc[mt][nt][3] * inv1)));
                *(float2*)(o + (size_t)(grow0 + 8) * DIM + col) = v1;
            }
        }
    }
}

// ---------------------------------------------------------------------------
extern "C" void kernel_launch(void* const* d_in, const int* in_sizes, int n_in,
                              void* d_out, int out_size)
{
    const float* x  = (const float*)d_in[0];
    const float* wq = (const float*)d_in[1];
    const float* bq = (const float*)d_in[2];
    const float* wk = (const float*)d_in[3];
    const float* bk = (const float*)d_in[4];
    const float* wv = (const float*)d_in[5];
    const float* bv = (const float*)d_in[6];
    const float* wo = (const float*)d_in[7];
    const float* bo = (const float*)d_in[8];
    const float* gq = (const float*)d_in[9];
    const float* gk = (const float*)d_in[10];
    const int* seq_lens = (const int*)d_in[12];
    float* out = (float*)d_out;

    float *qp, *kp, *vp, *op, *xp, *wqp, *wkp, *wvp, *wop;
    cudaGetSymbolAddress((void**)&qp, g_q);
    cudaGetSymbolAddress((void**)&kp, g_k);
    cudaGetSymbolAddress((void**)&vp, g_v);
    cudaGetSymbolAddress((void**)&op, g_o);
    cudaGetSymbolAddress((void**)&xp, g_x);
    cudaGetSymbolAddress((void**)&wqp, g_wq);
    cudaGetSymbolAddress((void**)&wkp, g_wk);
    cudaGetSymbolAddress((void**)&wvp, g_wv);
    cudaGetSymbolAddress((void**)&wop, g_wo);

    // fused pre-round of x + 4 weights
    pre_round5<<<(PR_TOTAL + 255) / 256, 256>>>(x, xp, wq, wqp, wk, wkp,
                                                wv, wvp, wo, wop);

    // fused Q/K/V projections (tf32-rounded outputs)
    dim3 gqkv(DIM / 128, (S_LEN + 127) / 128, 3);
    gemm_nt_tf32<<<gqkv, 128>>>(xp, wqp, wkp, wvp, bq, bk, bv, qp, kp, vp,
                                S_LEN, DIM, DIM, 1);

    rmsrope_kernel<<<S_LEN, 256>>>(qp, kp, gq, gk);

    cudaFuncSetAttribute(flash_tf32, cudaFuncAttributeMaxDynamicSharedMemorySize,
                         FL_SMEM_BYTES);
    flash_tf32<<<dim3((S_LEN + QT - 1) / QT, NH), 256, FL_SMEM_BYTES>>>(
        qp, kp, vp, op, seq_lens);

    // output projection (fp32 output)
    dim3 go(DIM / 128, (S_LEN + 127) / 128, 1);
    gemm_nt_tf32<<<go, 128>>>(op, wop, wop, wop, bo, bo, bo, out, out, out,
                              S_LEN, DIM, DIM, 0);
}